// round 14
// baseline (speedup 1.0000x reference)
#include <cuda_runtime.h>
#include <cuda_bf16.h>
#include <cstdint>

// Problem constants (fixed shapes from reference)
#define M_TOTAL 16384   // B*L
#define D_K     1024    // D
#define Q_N     256     // Q
#define C_N     4096    // C

#define CAND_MAX 32
#define RESCUE_DELTA 24.0f

// Scratch (device globals: allowed; no allocation APIs)
__device__ float          g_cbsq[C_N];            // ||codebook[:,c]||^2 (fp32 exact)
__device__ __nv_bfloat16  g_Wb[Q_N * D_K];        // bf16 W (512KB)
__device__ uint8_t        g_T8[M_TOTAL * Q_N];    // e4m3 targets (4MB), [r][k]
__device__ uint8_t        g_CB8[C_N * Q_N];       // e4m3 codebook (1MB), [c][k]
__device__ float          g_U[(size_t)C_N * D_K]; // U[c][d] = sum_q CB[q][c] W[q][d] (16MB)
__device__ int            g_ncand[M_TOTAL];
__device__ uint16_t       g_cand[M_TOTAL][CAND_MAX];

// ---------------- packed fp32x2 helpers (FFMA2, validated R5/R7) ----------------
__device__ __forceinline__ void fma2(unsigned long long& d,
                                     unsigned long long a,
                                     unsigned long long b) {
    asm("fma.rn.f32x2 %0, %1, %2, %0;" : "+l"(d) : "l"(a), "l"(b));
}
__device__ __forceinline__ unsigned long long pack2(float x) {
    unsigned long long r;
    unsigned u = __float_as_uint(x);
    asm("mov.b64 %0, {%1, %2};" : "=l"(r) : "r"(u), "r"(u));
    return r;
}
__device__ __forceinline__ float lo32(unsigned long long v) {
    return __uint_as_float((unsigned)(v & 0xffffffffull));
}
__device__ __forceinline__ float hi32(unsigned long long v) {
    return __uint_as_float((unsigned)(v >> 32));
}

// ---------------- warp MMA + ldmatrix + cp.async ----------------
__device__ __forceinline__ void mma16816(float* d, const uint32_t* a, const uint32_t* b) {
    asm volatile(
        "mma.sync.aligned.m16n8k16.row.col.f32.bf16.bf16.f32 "
        "{%0,%1,%2,%3}, {%4,%5,%6,%7}, {%8,%9}, {%0,%1,%2,%3};"
        : "+f"(d[0]), "+f"(d[1]), "+f"(d[2]), "+f"(d[3])
        : "r"(a[0]), "r"(a[1]), "r"(a[2]), "r"(a[3]), "r"(b[0]), "r"(b[1]));
}
__device__ __forceinline__ void mma16832f8(float* d, const uint32_t* a, const uint32_t* b) {
    asm volatile(
        "mma.sync.aligned.m16n8k32.row.col.f32.e4m3.e4m3.f32 "
        "{%0,%1,%2,%3}, {%4,%5,%6,%7}, {%8,%9}, {%0,%1,%2,%3};"
        : "+f"(d[0]), "+f"(d[1]), "+f"(d[2]), "+f"(d[3])
        : "r"(a[0]), "r"(a[1]), "r"(a[2]), "r"(a[3]), "r"(b[0]), "r"(b[1]));
}
__device__ __forceinline__ void ldsm_x4(uint32_t* r, uint32_t addr) {
    asm volatile("ldmatrix.sync.aligned.m8n8.x4.shared.b16 {%0,%1,%2,%3}, [%4];"
                 : "=r"(r[0]), "=r"(r[1]), "=r"(r[2]), "=r"(r[3]) : "r"(addr));
}
__device__ __forceinline__ void cp_async16(uint32_t dst, const void* src) {
    asm volatile("cp.async.cg.shared.global [%0], [%1], 16;" :: "r"(dst), "l"(src));
}
#define CP_COMMIT() asm volatile("cp.async.commit_group;" ::: "memory")
#define CP_WAIT0()  asm volatile("cp.async.wait_group 0;" ::: "memory")

__device__ __forceinline__ uint16_t cvt_e4m3x2(float hi, float lo) {
    uint16_t h;
    asm("cvt.rn.satfinite.e4m3x2.f32 %0, %1, %2;" : "=h"(h) : "f"(hi), "f"(lo));
    return h;
}

// order-preserving float<->uint key (for atomicMin on scores of any sign)
__device__ __forceinline__ uint32_t fkey(float f) {
    uint32_t b = __float_as_uint(f);
    return (b & 0x80000000u) ? ~b : (b | 0x80000000u);
}
__device__ __forceinline__ float funkey(uint32_t k) {
    uint32_t b = (k & 0x80000000u) ? (k & 0x7FFFFFFFu) : ~k;
    return __uint_as_float(b);
}

// ---------------- prep kernel: cbsq + convCB(fp8) + convW fused ----------------
// blocks [0,64): cbsq | [64,2112): CB->e4m3 [c][k] | [2112,2368): W->bf16
__global__ __launch_bounds__(256) void prep_kernel(const float* __restrict__ CB,
                                                   const float* __restrict__ W) {
    __shared__ float red[4][64];
    int b = blockIdx.x;
    int t = threadIdx.x;
    if (b < 64) {
        int c = b * 64 + (t & 63);
        int part = t >> 6;
        float s = 0.f;
        #pragma unroll 8
        for (int k = part * 64; k < part * 64 + 64; k++) {
            float v = CB[(size_t)k * C_N + c];
            s = fmaf(v, v, s);
        }
        red[part][t & 63] = s;
        __syncthreads();
        if (t < 64)
            g_cbsq[b * 64 + t] = red[0][t] + red[1][t] + red[2][t] + red[3][t];
    } else if (b < 2112) {
        int o2 = (b - 64) * 256 + t;        // pair index over 512K pairs
        int c  = o2 >> 7;
        int k2 = (o2 & 127) << 1;
        float f0 = CB[(size_t)k2 * C_N + c];
        float f1 = CB[(size_t)(k2 + 1) * C_N + c];
        *(uint16_t*)(g_CB8 + (size_t)c * Q_N + k2) = cvt_e4m3x2(f1, f0);
    } else {
        int idx = (b - 2112) * 256 + t;
        float4 v = ((const float4*)W)[idx];
        __nv_bfloat162* o = (__nv_bfloat162*)g_Wb + idx * 2;
        o[0] = __nv_bfloat162(__float2bfloat16(v.x), __float2bfloat16(v.y));
        o[1] = __nv_bfloat162(__float2bfloat16(v.z), __float2bfloat16(v.w));
    }
}

// ---------------- kernel U: U = CB^T @ W  (fp32 FFMA2, validated R11) ----------------
__global__ __launch_bounds__(256) void ugemm_kernel(const float* __restrict__ CB,
                                                    const float* __restrict__ W) {
    __shared__ __align__(16) float As[32][128];
    __shared__ __align__(16) float Bs[32][64];
    int tid = threadIdx.x;
    int tr = tid >> 4;
    int tc = tid & 15;
    int row0 = blockIdx.x << 7;   // c
    int col0 = blockIdx.y << 6;   // d

    unsigned long long acc[4][4];
    #pragma unroll
    for (int p = 0; p < 4; p++)
        #pragma unroll
        for (int j = 0; j < 4; j++) acc[p][j] = 0ull;

    for (int kc = 0; kc < Q_N; kc += 32) {
        __syncthreads();
        #pragma unroll
        for (int i = 0; i < 4; i++) {
            int f4 = (i << 8) + tid;
            int q  = f4 >> 5;
            int e4 = (f4 & 31) << 2;
            *(float4*)&As[q][e4] = *(const float4*)(CB + (size_t)(kc + q) * C_N + row0 + e4);
        }
        #pragma unroll
        for (int i = 0; i < 2; i++) {
            int f4 = (i << 8) + tid;
            int q  = f4 >> 4;
            int e4 = (f4 & 15) << 2;
            *(float4*)&Bs[q][e4] = *(const float4*)(W + (size_t)(kc + q) * D_K + col0 + e4);
        }
        __syncthreads();
        #pragma unroll
        for (int k = 0; k < 32; k++) {
            ulonglong2 a01 = *(const ulonglong2*)&As[k][tr << 3];
            ulonglong2 a23 = *(const ulonglong2*)&As[k][(tr << 3) + 4];
            float4 b = *(const float4*)&Bs[k][tc << 2];
            unsigned long long bb0 = pack2(b.x), bb1 = pack2(b.y);
            unsigned long long bb2 = pack2(b.z), bb3 = pack2(b.w);
            fma2(acc[0][0], a01.x, bb0); fma2(acc[0][1], a01.x, bb1);
            fma2(acc[0][2], a01.x, bb2); fma2(acc[0][3], a01.x, bb3);
            fma2(acc[1][0], a01.y, bb0); fma2(acc[1][1], a01.y, bb1);
            fma2(acc[1][2], a01.y, bb2); fma2(acc[1][3], a01.y, bb3);
            fma2(acc[2][0], a23.x, bb0); fma2(acc[2][1], a23.x, bb1);
            fma2(acc[2][2], a23.x, bb2); fma2(acc[2][3], a23.x, bb3);
            fma2(acc[3][0], a23.y, bb0); fma2(acc[3][1], a23.y, bb1);
            fma2(acc[3][2], a23.y, bb2); fma2(acc[3][3], a23.y, bb3);
        }
    }
    #pragma unroll
    for (int p = 0; p < 4; p++) {
        int c = row0 + (tr << 3) + (p << 1);
        #pragma unroll
        for (int j = 0; j < 4; j++) {
            int d = col0 + (tc << 2) + j;
            g_U[(size_t)c       * D_K + d] = lo32(acc[p][j]);
            g_U[(size_t)(c + 1) * D_K + d] = hi32(acc[p][j]);
        }
    }
}

// ---------------- kernel 1: T = bf16 gemm, OUTPUT e4m3 (fp8) ----------------
#define T_STRIDE 72
__global__ __launch_bounds__(256, 2) void gemm1b_kernel(const float* __restrict__ X) {
    __shared__ __align__(16) __nv_bfloat16 As[128][T_STRIDE];
    __shared__ __align__(16) __nv_bfloat16 Bs[128][T_STRIDE];

    int tid  = threadIdx.x;
    int wid  = tid >> 5;
    int lane = tid & 31;
    int q    = lane >> 2;
    int tig  = lane & 3;
    int wm   = wid & 3;
    int wn   = wid >> 2;
    int row0 = blockIdx.x << 7;
    int col0 = blockIdx.y << 7;

    int g   = lane >> 3, idx = lane & 7;
    uint32_t aaddr[2], baddr[4];
    #pragma unroll
    for (int i = 0; i < 2; i++) {
        int r = wm * 32 + i * 16 + ((g & 1) << 3) + idx;
        aaddr[i] = (uint32_t)__cvta_generic_to_shared(&As[r][(g >> 1) << 3]);
    }
    #pragma unroll
    for (int jp = 0; jp < 4; jp++) {
        int r = wn * 64 + jp * 16 + ((g >> 1) << 3) + idx;
        baddr[jp] = (uint32_t)__cvta_generic_to_shared(&Bs[r][(g & 1) << 3]);
    }

    float d[2][8][4];
    #pragma unroll
    for (int i = 0; i < 2; i++)
        #pragma unroll
        for (int j = 0; j < 8; j++)
            #pragma unroll
            for (int e = 0; e < 4; e++) d[i][j][e] = 0.f;

    for (int kc = 0; kc < D_K; kc += 64) {
        __syncthreads();
        #pragma unroll
        for (int i = 0; i < 8; i++) {
            int fi  = (i << 8) + tid;
            int row = fi >> 4;
            int c4  = (fi & 15) << 2;
            float4 v = *(const float4*)(X + (size_t)(row0 + row) * D_K + kc + c4);
            *(__nv_bfloat162*)&As[row][c4] =
                __nv_bfloat162(__float2bfloat16(v.x), __float2bfloat16(v.y));
            *(__nv_bfloat162*)&As[row][c4 + 2] =
                __nv_bfloat162(__float2bfloat16(v.z), __float2bfloat16(v.w));
        }
        #pragma unroll
        for (int i = 0; i < 4; i++) {
            int id  = (i << 8) + tid;
            int row = id >> 3;
            int k8  = (id & 7) << 3;
            *(uint4*)&Bs[row][k8] = *(const uint4*)(g_Wb + (size_t)(col0 + row) * D_K + kc + k8);
        }
        __syncthreads();
        #pragma unroll
        for (int ks = 0; ks < 4; ks++) {
            uint32_t koff = (uint32_t)(ks * 16 * 2);
            uint32_t a[2][4], b[4][4];
            ldsm_x4(a[0], aaddr[0] + koff);
            ldsm_x4(a[1], aaddr[1] + koff);
            #pragma unroll
            for (int jp = 0; jp < 4; jp++) ldsm_x4(b[jp], baddr[jp] + koff);
            #pragma unroll
            for (int i = 0; i < 2; i++)
                #pragma unroll
                for (int jp = 0; jp < 4; jp++) {
                    mma16816(d[i][jp * 2 + 0], a[i], &b[jp][0]);
                    mma16816(d[i][jp * 2 + 1], a[i], &b[jp][2]);
                }
        }
    }
    // epilogue: e4m3 pair stores
    #pragma unroll
    for (int j = 0; j < 8; j++) {
        int c = col0 + wn * 64 + j * 8 + tig * 2;
        #pragma unroll
        for (int i = 0; i < 2; i++) {
            int r = row0 + wm * 32 + i * 16 + q;
            *(uint16_t*)(g_T8 + (size_t)r * Q_N + c)       = cvt_e4m3x2(d[i][j][1], d[i][j][0]);
            *(uint16_t*)(g_T8 + (size_t)(r + 8) * Q_N + c) = cvt_e4m3x2(d[i][j][3], d[i][j][2]);
        }
    }
}

// ---------------- kernel 2: fp8 filter GEMM, BM=64, 2 CTAs/SM ----------------
#define A8STRIDE 272           // bytes per row (256 + 16 pad): conflict-free ldsm
#define G2_BM   64
#define G2_BN   128
#define G2_THREADS 256
#define G2_SMEM ((G2_BM + G2_BN) * A8STRIDE)   // 52224 bytes dynamic
#define NT_CNT  (C_N / G2_BN)                   // 32

__global__ __launch_bounds__(G2_THREADS, 2) void gemm2_tc_kernel() {
    extern __shared__ __align__(16) uint8_t sm8[];
    uint8_t* As = sm8;                        // [64][272]
    uint8_t* Bs = sm8 + G2_BM * A8STRIDE;     // [128][272]
    __shared__ uint32_t s_rowkey[G2_BM];
    __shared__ int      s_cnt[G2_BM];
    __shared__ uint16_t s_cand[G2_BM][CAND_MAX];

    int tid  = threadIdx.x;
    int lane = tid & 31;
    int wid  = tid >> 5;       // 0..7
    int q    = lane >> 2;
    int tig  = lane & 3;
    int wm   = wid & 1;        // rows wm*32..+31
    int wn   = wid >> 1;       // cols wn*32..+31 within 128-chunk
    int row0 = blockIdx.x * G2_BM;

    if (tid < G2_BM) { s_rowkey[tid] = 0xFFFFFFFFu; s_cnt[tid] = 0; }

    // stage resident A: 64 rows x 16 uint4 = 1024 uint4 / 256 thr = 4 each
    #pragma unroll
    for (int i = 0; i < 4; i++) {
        int id  = (i << 8) + tid;
        int row = id >> 4;
        int kb  = (id & 15) << 4;
        *(uint4*)(As + row * A8STRIDE + kb) =
            *(const uint4*)(g_T8 + (size_t)(row0 + row) * Q_N + kb);
    }

    uint32_t bsb = (uint32_t)__cvta_generic_to_shared(Bs);

    // ldmatrix lane addresses (fp8: byte-contiguous fake-b16 tiles)
    int g = lane >> 3, idx = lane & 7;
    uint32_t aaddr[2], baddr[2];
    #pragma unroll
    for (int i = 0; i < 2; i++) {
        // matrices: g0 rows0-7/bytes0-15 (a0), g1 rows8-15/bytes0-15 (a1),
        //           g2 rows0-7/bytes16-31 (a2), g3 rows8-15/bytes16-31 (a3)
        int r = wm * 32 + i * 16 + ((g & 1) << 3) + idx;
        aaddr[i] = (uint32_t)__cvta_generic_to_shared(As + r * A8STRIDE + ((g >> 1) << 4));
    }
    #pragma unroll
    for (int jp = 0; jp < 2; jp++) {
        // matrices: g0 n0-7/k0-15 (b0 of ntile0), g1 n0-7/k16-31 (b1),
        //           g2 n8-15/k0-15, g3 n8-15/k16-31
        int r = wn * 32 + jp * 16 + ((g >> 1) << 3) + idx;
        baddr[jp] = bsb + (uint32_t)(r * A8STRIDE + ((g & 1) << 4));
    }

    // cp.async B staging: 128 rows x 16 uint4 = 2048 / 256 thr = 8 each
    #define ISSUE_B(nt_)                                                            \
        do {                                                                        \
            const uint8_t* src = g_CB8 + (size_t)((nt_) * G2_BN) * Q_N;             \
            _Pragma("unroll")                                                       \
            for (int i_ = 0; i_ < 8; i_++) {                                        \
                int id_  = (i_ << 8) + tid;                                         \
                int row_ = id_ >> 4;                                                \
                int kb_  = (id_ & 15) << 4;                                         \
                cp_async16(bsb + (uint32_t)(row_ * A8STRIDE + kb_),                 \
                           src + (size_t)row_ * Q_N + kb_);                         \
            }                                                                       \
        } while (0)

    ISSUE_B(0); CP_COMMIT();

    int lr[2][2];
    #pragma unroll
    for (int i = 0; i < 2; i++) {
        lr[i][0] = wm * 32 + i * 16 + q;
        lr[i][1] = lr[i][0] + 8;
    }

    for (int nt = 0; nt < NT_CNT; nt++) {
        CP_WAIT0();
        __syncthreads();     // B(nt) staged; also covers A/init on nt==0

        float d[2][4][4];
        #pragma unroll
        for (int i = 0; i < 2; i++)
            #pragma unroll
            for (int j = 0; j < 4; j++)
                #pragma unroll
                for (int e = 0; e < 4; e++) d[i][j][e] = 0.f;

        #pragma unroll
        for (int ks = 0; ks < 8; ks++) {      // K=256, 32 per mma
            uint32_t koff = (uint32_t)(ks * 32);
            uint32_t a[2][4], b[2][4];
            ldsm_x4(a[0], aaddr[0] + koff);
            ldsm_x4(a[1], aaddr[1] + koff);
            ldsm_x4(b[0], baddr[0] + koff);
            ldsm_x4(b[1], baddr[1] + koff);
            #pragma unroll
            for (int i = 0; i < 2; i++) {
                mma16832f8(d[i][0], a[i], &b[0][0]);   // n 0-7
                mma16832f8(d[i][1], a[i], &b[0][2]);   // n 8-15
                mma16832f8(d[i][2], a[i], &b[1][0]);   // n 16-23
                mma16832f8(d[i][3], a[i], &b[1][2]);   // n 24-31
            }
        }

        // epilogue phase 1: per-row local min -> shared atomicMin
        int cbase = nt * G2_BN + wn * 32;
        float cq[4][2];
        #pragma unroll
        for (int j = 0; j < 4; j++) {
            cq[j][0] = g_cbsq[cbase + j * 8 + tig * 2];
            cq[j][1] = g_cbsq[cbase + j * 8 + tig * 2 + 1];
        }
        float lmin[2][2] = {{3.4e38f, 3.4e38f}, {3.4e38f, 3.4e38f}};
        #pragma unroll
        for (int i = 0; i < 2; i++)
            #pragma unroll
            for (int j = 0; j < 4; j++) {
                float s00 = fmaf(-2.f, d[i][j][0], cq[j][0]);
                float s01 = fmaf(-2.f, d[i][j][1], cq[j][1]);
                float s10 = fmaf(-2.f, d[i][j][2], cq[j][0]);
                float s11 = fmaf(-2.f, d[i][j][3], cq[j][1]);
                lmin[i][0] = fminf(lmin[i][0], fminf(s00, s01));
                lmin[i][1] = fminf(lmin[i][1], fminf(s10, s11));
            }
        #pragma unroll
        for (int i = 0; i < 2; i++) {
            atomicMin(&s_rowkey[lr[i][0]], fkey(lmin[i][0]));
            atomicMin(&s_rowkey[lr[i][1]], fkey(lmin[i][1]));
        }
        __syncthreads();     // mins folded; ALL warps done reading Bs

        // issue B(nt+1) (safe post-barrier; overlaps register epilogue + peer CTA)
        if (nt + 1 < NT_CNT) ISSUE_B(nt + 1);
        CP_COMMIT();

        // epilogue phase 2: insert candidates vs tightened threshold
        #pragma unroll
        for (int i = 0; i < 2; i++)
            #pragma unroll
            for (int h = 0; h < 2; h++) {
                float thr = funkey(s_rowkey[lr[i][h]]) + RESCUE_DELTA;
                #pragma unroll
                for (int j = 0; j < 4; j++) {
                    float sa = fmaf(-2.f, d[i][j][h * 2 + 0], cq[j][0]);
                    float sb = fmaf(-2.f, d[i][j][h * 2 + 1], cq[j][1]);
                    int c = cbase + j * 8 + tig * 2;
                    if (sa <= thr) {
                        int pos = atomicAdd(&s_cnt[lr[i][h]], 1);
                        if (pos < CAND_MAX) s_cand[lr[i][h]][pos] = (uint16_t)c;
                    }
                    if (sb <= thr) {
                        int pos = atomicAdd(&s_cnt[lr[i][h]], 1);
                        if (pos < CAND_MAX) s_cand[lr[i][h]][pos] = (uint16_t)(c + 1);
                    }
                }
            }
    }

    __syncthreads();
    if (tid < G2_BM) {
        g_ncand[row0 + tid] = s_cnt[tid];
        #pragma unroll
        for (int i = 0; i < CAND_MAX / 8; i++)
            *(uint4*)&g_cand[row0 + tid][i * 8] = *(uint4*)&s_cand[tid][i * 8];
    }
}

// ---------------- kernel 3: exact rescue over candidates (validated R9-R13) ----------------
__global__ __launch_bounds__(256) void rescue_kernel(const float* __restrict__ X,
                                                     float* __restrict__ out) {
    int wid  = threadIdx.x >> 5;
    int lane = threadIdx.x & 31;
    int row  = blockIdx.x * 8 + wid;

    const float* xrow = X + (size_t)row * D_K;
    float x[32];
    #pragma unroll
    for (int t = 0; t < 32; t++) x[t] = xrow[lane + t * 32];

    float bestv = 3.4e38f;
    int   besti = C_N;
    int n = g_ncand[row];

    if (n <= CAND_MAX) {
        for (int i = 0; i < n; i++) {
            int c = g_cand[row][i];
            const float* urow = g_U + (size_t)c * D_K;
            float part = 0.f;
            #pragma unroll 8
            for (int t = 0; t < 32; t++)
                part = fmaf(x[t], urow[lane + t * 32], part);
            #pragma unroll
            for (int off = 16; off > 0; off >>= 1)
                part += __shfl_xor_sync(0xffffffffu, part, off);
            float sc = fmaf(-2.f, part, g_cbsq[c]);
            if (sc < bestv || (sc == bestv && c < besti)) { bestv = sc; besti = c; }
        }
    } else {
        for (int c = 0; c < C_N; c++) {
            const float* urow = g_U + (size_t)c * D_K;
            float part = 0.f;
            #pragma unroll 8
            for (int t = 0; t < 32; t++)
                part = fmaf(x[t], urow[lane + t * 32], part);
            #pragma unroll
            for (int off = 16; off > 0; off >>= 1)
                part += __shfl_xor_sync(0xffffffffu, part, off);
            float sc = fmaf(-2.f, part, g_cbsq[c]);
            if (sc < bestv) { bestv = sc; besti = c; }
        }
    }
    if (lane == 0) out[row] = (float)besti;
}

// ---------------- launch ----------------
extern "C" void kernel_launch(void* const* d_in, const int* in_sizes, int n_in,
                              void* d_out, int out_size) {
    (void)out_size;
    const float* X  = 0;
    const float* W  = 0;
    const float* CB = 0;
    for (int i = 0; i < n_in; i++) {
        long long s = (long long)in_sizes[i];
        if      (s == (long long)M_TOTAL * D_K) X  = (const float*)d_in[i];
        else if (s == (long long)Q_N * D_K)     W  = (const float*)d_in[i];
        else if (s == (long long)Q_N * C_N)     CB = (const float*)d_in[i];
    }
    if (!X)  X  = (const float*)d_in[0];
    if (!W  && n_in > 2) W  = (const float*)d_in[2];
    if (!CB && n_in > 3) CB = (const float*)d_in[3];

    float* out = (float*)d_out;

    cudaFuncSetAttribute(gemm2_tc_kernel,
                         cudaFuncAttributeMaxDynamicSharedMemorySize, G2_SMEM);

    prep_kernel<<<64 + 2048 + 256, 256>>>(CB, W);
    ugemm_kernel<<<dim3(C_N / 128, D_K / 64), 256>>>(CB, W);
    gemm1b_kernel<<<dim3(M_TOTAL / 128, Q_N / 128), 256>>>(X);
    gemm2_tc_kernel<<<M_TOTAL / G2_BM, G2_THREADS, G2_SMEM>>>();
    rescue_kernel<<<M_TOTAL / 8, 256>>>(X, out);
}

// round 15
// speedup vs baseline: 35.6868x; 35.6868x over previous
#include <cuda_runtime.h>
#include <cuda_bf16.h>
#include <cstdint>

// Problem constants (fixed shapes from reference)
#define M_TOTAL 16384   // B*L
#define D_K     1024    // D
#define Q_N     256     // Q
#define C_N     4096    // C

#define CAND_MAX 32
#define RESCUE_DELTA 8.0f
#define T_SCALE  18.0f
#define CB_SCALE 23.0f
#define SCORE_K  (2.0f / (T_SCALE * CB_SCALE))

// Scratch (device globals: allowed; no allocation APIs)
__device__ float          g_cbsq[C_N];            // ||codebook[:,c]||^2 (fp32 exact)
__device__ __nv_bfloat16  g_Wb[Q_N * D_K];        // bf16 W (512KB)
__device__ int8_t         g_T8[M_TOTAL * Q_N];    // int8 targets (4MB), [r][k]
__device__ int8_t         g_CB8[C_N * Q_N];       // int8 codebook (1MB), [c][k]
__device__ float          g_U[(size_t)C_N * D_K]; // U[c][d] = sum_q CB[q][c] W[q][d] (16MB)
__device__ int            g_ncand[M_TOTAL];
__device__ uint16_t       g_cand[M_TOTAL][CAND_MAX];

// ---------------- packed fp32x2 helpers (FFMA2, validated R5/R7) ----------------
__device__ __forceinline__ void fma2(unsigned long long& d,
                                     unsigned long long a,
                                     unsigned long long b) {
    asm("fma.rn.f32x2 %0, %1, %2, %0;" : "+l"(d) : "l"(a), "l"(b));
}
__device__ __forceinline__ unsigned long long pack2(float x) {
    unsigned long long r;
    unsigned u = __float_as_uint(x);
    asm("mov.b64 %0, {%1, %2};" : "=l"(r) : "r"(u), "r"(u));
    return r;
}
__device__ __forceinline__ float lo32(unsigned long long v) {
    return __uint_as_float((unsigned)(v & 0xffffffffull));
}
__device__ __forceinline__ float hi32(unsigned long long v) {
    return __uint_as_float((unsigned)(v >> 32));
}

// ---------------- warp MMA + ldmatrix + cp.async ----------------
__device__ __forceinline__ void mma16816(float* d, const uint32_t* a, const uint32_t* b) {
    asm volatile(
        "mma.sync.aligned.m16n8k16.row.col.f32.bf16.bf16.f32 "
        "{%0,%1,%2,%3}, {%4,%5,%6,%7}, {%8,%9}, {%0,%1,%2,%3};"
        : "+f"(d[0]), "+f"(d[1]), "+f"(d[2]), "+f"(d[3])
        : "r"(a[0]), "r"(a[1]), "r"(a[2]), "r"(a[3]), "r"(b[0]), "r"(b[1]));
}
__device__ __forceinline__ void mma16832s8(int* d, const uint32_t* a, const uint32_t* b) {
    asm volatile(
        "mma.sync.aligned.m16n8k32.row.col.s32.s8.s8.s32 "
        "{%0,%1,%2,%3}, {%4,%5,%6,%7}, {%8,%9}, {%0,%1,%2,%3};"
        : "+r"(d[0]), "+r"(d[1]), "+r"(d[2]), "+r"(d[3])
        : "r"(a[0]), "r"(a[1]), "r"(a[2]), "r"(a[3]), "r"(b[0]), "r"(b[1]));
}
__device__ __forceinline__ void ldsm_x4(uint32_t* r, uint32_t addr) {
    asm volatile("ldmatrix.sync.aligned.m8n8.x4.shared.b16 {%0,%1,%2,%3}, [%4];"
                 : "=r"(r[0]), "=r"(r[1]), "=r"(r[2]), "=r"(r[3]) : "r"(addr));
}
__device__ __forceinline__ void cp_async16(uint32_t dst, const void* src) {
    asm volatile("cp.async.cg.shared.global [%0], [%1], 16;" :: "r"(dst), "l"(src));
}
#define CP_COMMIT() asm volatile("cp.async.commit_group;" ::: "memory")
#define CP_WAIT0()  asm volatile("cp.async.wait_group 0;" ::: "memory")

__device__ __forceinline__ int q8(float v, float s) {
    int q = __float2int_rn(v * s);
    return q < -127 ? -127 : (q > 127 ? 127 : q);
}

// order-preserving float<->uint key (for atomicMin on scores of any sign)
__device__ __forceinline__ uint32_t fkey(float f) {
    uint32_t b = __float_as_uint(f);
    return (b & 0x80000000u) ? ~b : (b | 0x80000000u);
}
__device__ __forceinline__ float funkey(uint32_t k) {
    uint32_t b = (k & 0x80000000u) ? (k & 0x7FFFFFFFu) : ~k;
    return __uint_as_float(b);
}

// ---------------- prep kernel: cbsq + convCB(int8) + convW fused ----------------
// blocks [0,64): cbsq | [64,2112): CB->s8 [c][k] | [2112,2368): W->bf16
__global__ __launch_bounds__(256) void prep_kernel(const float* __restrict__ CB,
                                                   const float* __restrict__ W) {
    __shared__ float red[4][64];
    int b = blockIdx.x;
    int t = threadIdx.x;
    if (b < 64) {
        int c = b * 64 + (t & 63);
        int part = t >> 6;
        float s = 0.f;
        #pragma unroll 8
        for (int k = part * 64; k < part * 64 + 64; k++) {
            float v = CB[(size_t)k * C_N + c];
            s = fmaf(v, v, s);
        }
        red[part][t & 63] = s;
        __syncthreads();
        if (t < 64)
            g_cbsq[b * 64 + t] = red[0][t] + red[1][t] + red[2][t] + red[3][t];
    } else if (b < 2112) {
        int o2 = (b - 64) * 256 + t;        // pair index over 512K pairs
        int c  = o2 >> 7;
        int k2 = (o2 & 127) << 1;
        int q0 = q8(CB[(size_t)k2 * C_N + c], CB_SCALE);
        int q1 = q8(CB[(size_t)(k2 + 1) * C_N + c], CB_SCALE);
        *(uint16_t*)(g_CB8 + (size_t)c * Q_N + k2) =
            (uint16_t)((q0 & 0xFF) | ((q1 & 0xFF) << 8));
    } else {
        int idx = (b - 2112) * 256 + t;
        float4 v = ((const float4*)W)[idx];
        __nv_bfloat162* o = (__nv_bfloat162*)g_Wb + idx * 2;
        o[0] = __nv_bfloat162(__float2bfloat16(v.x), __float2bfloat16(v.y));
        o[1] = __nv_bfloat162(__float2bfloat16(v.z), __float2bfloat16(v.w));
    }
}

// ---------------- kernel U: U = CB^T @ W  (fp32 FFMA2, validated R11) ----------------
__global__ __launch_bounds__(256) void ugemm_kernel(const float* __restrict__ CB,
                                                    const float* __restrict__ W) {
    __shared__ __align__(16) float As[32][128];
    __shared__ __align__(16) float Bs[32][64];
    int tid = threadIdx.x;
    int tr = tid >> 4;
    int tc = tid & 15;
    int row0 = blockIdx.x << 7;   // c
    int col0 = blockIdx.y << 6;   // d

    unsigned long long acc[4][4];
    #pragma unroll
    for (int p = 0; p < 4; p++)
        #pragma unroll
        for (int j = 0; j < 4; j++) acc[p][j] = 0ull;

    for (int kc = 0; kc < Q_N; kc += 32) {
        __syncthreads();
        #pragma unroll
        for (int i = 0; i < 4; i++) {
            int f4 = (i << 8) + tid;
            int q  = f4 >> 5;
            int e4 = (f4 & 31) << 2;
            *(float4*)&As[q][e4] = *(const float4*)(CB + (size_t)(kc + q) * C_N + row0 + e4);
        }
        #pragma unroll
        for (int i = 0; i < 2; i++) {
            int f4 = (i << 8) + tid;
            int q  = f4 >> 4;
            int e4 = (f4 & 15) << 2;
            *(float4*)&Bs[q][e4] = *(const float4*)(W + (size_t)(kc + q) * D_K + col0 + e4);
        }
        __syncthreads();
        #pragma unroll
        for (int k = 0; k < 32; k++) {
            ulonglong2 a01 = *(const ulonglong2*)&As[k][tr << 3];
            ulonglong2 a23 = *(const ulonglong2*)&As[k][(tr << 3) + 4];
            float4 b = *(const float4*)&Bs[k][tc << 2];
            unsigned long long bb0 = pack2(b.x), bb1 = pack2(b.y);
            unsigned long long bb2 = pack2(b.z), bb3 = pack2(b.w);
            fma2(acc[0][0], a01.x, bb0); fma2(acc[0][1], a01.x, bb1);
            fma2(acc[0][2], a01.x, bb2); fma2(acc[0][3], a01.x, bb3);
            fma2(acc[1][0], a01.y, bb0); fma2(acc[1][1], a01.y, bb1);
            fma2(acc[1][2], a01.y, bb2); fma2(acc[1][3], a01.y, bb3);
            fma2(acc[2][0], a23.x, bb0); fma2(acc[2][1], a23.x, bb1);
            fma2(acc[2][2], a23.x, bb2); fma2(acc[2][3], a23.x, bb3);
            fma2(acc[3][0], a23.y, bb0); fma2(acc[3][1], a23.y, bb1);
            fma2(acc[3][2], a23.y, bb2); fma2(acc[3][3], a23.y, bb3);
        }
    }
    #pragma unroll
    for (int p = 0; p < 4; p++) {
        int c = row0 + (tr << 3) + (p << 1);
        #pragma unroll
        for (int j = 0; j < 4; j++) {
            int d = col0 + (tc << 2) + j;
            g_U[(size_t)c       * D_K + d] = lo32(acc[p][j]);
            g_U[(size_t)(c + 1) * D_K + d] = hi32(acc[p][j]);
        }
    }
}

// ---------------- kernel 1: T = bf16 gemm, OUTPUT int8 ----------------
#define T_STRIDE 72
__global__ __launch_bounds__(256, 2) void gemm1b_kernel(const float* __restrict__ X) {
    __shared__ __align__(16) __nv_bfloat16 As[128][T_STRIDE];
    __shared__ __align__(16) __nv_bfloat16 Bs[128][T_STRIDE];

    int tid  = threadIdx.x;
    int wid  = tid >> 5;
    int lane = tid & 31;
    int q    = lane >> 2;
    int tig  = lane & 3;
    int wm   = wid & 3;
    int wn   = wid >> 2;
    int row0 = blockIdx.x << 7;
    int col0 = blockIdx.y << 7;

    int g   = lane >> 3, idx = lane & 7;
    uint32_t aaddr[2], baddr[4];
    #pragma unroll
    for (int i = 0; i < 2; i++) {
        int r = wm * 32 + i * 16 + ((g & 1) << 3) + idx;
        aaddr[i] = (uint32_t)__cvta_generic_to_shared(&As[r][(g >> 1) << 3]);
    }
    #pragma unroll
    for (int jp = 0; jp < 4; jp++) {
        int r = wn * 64 + jp * 16 + ((g >> 1) << 3) + idx;
        baddr[jp] = (uint32_t)__cvta_generic_to_shared(&Bs[r][(g & 1) << 3]);
    }

    float d[2][8][4];
    #pragma unroll
    for (int i = 0; i < 2; i++)
        #pragma unroll
        for (int j = 0; j < 8; j++)
            #pragma unroll
            for (int e = 0; e < 4; e++) d[i][j][e] = 0.f;

    for (int kc = 0; kc < D_K; kc += 64) {
        __syncthreads();
        #pragma unroll
        for (int i = 0; i < 8; i++) {
            int fi  = (i << 8) + tid;
            int row = fi >> 4;
            int c4  = (fi & 15) << 2;
            float4 v = *(const float4*)(X + (size_t)(row0 + row) * D_K + kc + c4);
            *(__nv_bfloat162*)&As[row][c4] =
                __nv_bfloat162(__float2bfloat16(v.x), __float2bfloat16(v.y));
            *(__nv_bfloat162*)&As[row][c4 + 2] =
                __nv_bfloat162(__float2bfloat16(v.z), __float2bfloat16(v.w));
        }
        #pragma unroll
        for (int i = 0; i < 4; i++) {
            int id  = (i << 8) + tid;
            int row = id >> 3;
            int k8  = (id & 7) << 3;
            *(uint4*)&Bs[row][k8] = *(const uint4*)(g_Wb + (size_t)(col0 + row) * D_K + kc + k8);
        }
        __syncthreads();
        #pragma unroll
        for (int ks = 0; ks < 4; ks++) {
            uint32_t koff = (uint32_t)(ks * 16 * 2);
            uint32_t a[2][4], b[4][4];
            ldsm_x4(a[0], aaddr[0] + koff);
            ldsm_x4(a[1], aaddr[1] + koff);
            #pragma unroll
            for (int jp = 0; jp < 4; jp++) ldsm_x4(b[jp], baddr[jp] + koff);
            #pragma unroll
            for (int i = 0; i < 2; i++)
                #pragma unroll
                for (int jp = 0; jp < 4; jp++) {
                    mma16816(d[i][jp * 2 + 0], a[i], &b[jp][0]);
                    mma16816(d[i][jp * 2 + 1], a[i], &b[jp][2]);
                }
        }
    }
    // epilogue: int8 pair stores (scale T_SCALE)
    #pragma unroll
    for (int j = 0; j < 8; j++) {
        int c = col0 + wn * 64 + j * 8 + tig * 2;
        #pragma unroll
        for (int i = 0; i < 2; i++) {
            int r = row0 + wm * 32 + i * 16 + q;
            int q0 = q8(d[i][j][0], T_SCALE), q1 = q8(d[i][j][1], T_SCALE);
            int q2 = q8(d[i][j][2], T_SCALE), q3 = q8(d[i][j][3], T_SCALE);
            *(uint16_t*)(g_T8 + (size_t)r * Q_N + c) =
                (uint16_t)((q0 & 0xFF) | ((q1 & 0xFF) << 8));
            *(uint16_t*)(g_T8 + (size_t)(r + 8) * Q_N + c) =
                (uint16_t)((q2 & 0xFF) | ((q3 & 0xFF) << 8));
        }
    }
}

// ---------------- kernel 2: int8 filter GEMM, BM=64, 2 CTAs/SM ----------------
#define A8STRIDE 272           // bytes per row (256 + 16 pad)
#define G2_BM   64
#define G2_BN   128
#define G2_THREADS 256
#define G2_SMEM ((G2_BM + G2_BN) * A8STRIDE)   // 52224 bytes dynamic
#define NT_CNT  (C_N / G2_BN)                   // 32

__global__ __launch_bounds__(G2_THREADS, 2) void gemm2_tc_kernel() {
    extern __shared__ __align__(16) uint8_t sm8[];
    uint8_t* As = sm8;                        // [64][272]
    uint8_t* Bs = sm8 + G2_BM * A8STRIDE;     // [128][272]
    __shared__ uint32_t s_rowkey[G2_BM];
    __shared__ int      s_cnt[G2_BM];
    __shared__ uint16_t s_cand[G2_BM][CAND_MAX];

    int tid  = threadIdx.x;
    int lane = tid & 31;
    int wid  = tid >> 5;       // 0..7
    int q    = lane >> 2;
    int tig  = lane & 3;
    int wm   = wid & 1;        // rows wm*32..+31
    int wn   = wid >> 1;       // cols wn*32..+31 within 128-chunk
    int row0 = blockIdx.x * G2_BM;

    if (tid < G2_BM) { s_rowkey[tid] = 0xFFFFFFFFu; s_cnt[tid] = 0; }

    // stage resident A: 64 rows x 16 uint4 = 1024 uint4 / 256 thr = 4 each
    #pragma unroll
    for (int i = 0; i < 4; i++) {
        int id  = (i << 8) + tid;
        int row = id >> 4;
        int kb  = (id & 15) << 4;
        *(uint4*)(As + row * A8STRIDE + kb) =
            *(const uint4*)(g_T8 + (size_t)(row0 + row) * Q_N + kb);
    }

    uint32_t bsb = (uint32_t)__cvta_generic_to_shared(Bs);

    // ldmatrix lane addresses (byte-contiguous fake-b16 tiles; s8-k32 fragments)
    int g = lane >> 3, idx = lane & 7;
    uint32_t aaddr[2], baddr[2];
    #pragma unroll
    for (int i = 0; i < 2; i++) {
        int r = wm * 32 + i * 16 + ((g & 1) << 3) + idx;
        aaddr[i] = (uint32_t)__cvta_generic_to_shared(As + r * A8STRIDE + ((g >> 1) << 4));
    }
    #pragma unroll
    for (int jp = 0; jp < 2; jp++) {
        int r = wn * 32 + jp * 16 + ((g >> 1) << 3) + idx;
        baddr[jp] = bsb + (uint32_t)(r * A8STRIDE + ((g & 1) << 4));
    }

    // cp.async B staging: 128 rows x 16 uint4 = 2048 / 256 thr = 8 each
    #define ISSUE_B(nt_)                                                            \
        do {                                                                        \
            const int8_t* src = g_CB8 + (size_t)((nt_) * G2_BN) * Q_N;              \
            _Pragma("unroll")                                                       \
            for (int i_ = 0; i_ < 8; i_++) {                                        \
                int id_  = (i_ << 8) + tid;                                         \
                int row_ = id_ >> 4;                                                \
                int kb_  = (id_ & 15) << 4;                                         \
                cp_async16(bsb + (uint32_t)(row_ * A8STRIDE + kb_),                 \
                           src + (size_t)row_ * Q_N + kb_);                         \
            }                                                                       \
        } while (0)

    ISSUE_B(0); CP_COMMIT();

    int lr[2][2];
    #pragma unroll
    for (int i = 0; i < 2; i++) {
        lr[i][0] = wm * 32 + i * 16 + q;
        lr[i][1] = lr[i][0] + 8;
    }

    for (int nt = 0; nt < NT_CNT; nt++) {
        CP_WAIT0();
        __syncthreads();     // B(nt) staged; also covers A/init on nt==0

        int d[2][4][4];
        #pragma unroll
        for (int i = 0; i < 2; i++)
            #pragma unroll
            for (int j = 0; j < 4; j++)
                #pragma unroll
                for (int e = 0; e < 4; e++) d[i][j][e] = 0;

        #pragma unroll
        for (int ks = 0; ks < 8; ks++) {      // K=256, 32 per mma
            uint32_t koff = (uint32_t)(ks * 32);
            uint32_t a[2][4], b[2][4];
            ldsm_x4(a[0], aaddr[0] + koff);
            ldsm_x4(a[1], aaddr[1] + koff);
            ldsm_x4(b[0], baddr[0] + koff);
            ldsm_x4(b[1], baddr[1] + koff);
            #pragma unroll
            for (int i = 0; i < 2; i++) {
                mma16832s8(d[i][0], a[i], &b[0][0]);   // n 0-7
                mma16832s8(d[i][1], a[i], &b[0][2]);   // n 8-15
                mma16832s8(d[i][2], a[i], &b[1][0]);   // n 16-23
                mma16832s8(d[i][3], a[i], &b[1][2]);   // n 24-31
            }
        }

        // epilogue phase 1: per-row local min -> shared atomicMin
        int cbase = nt * G2_BN + wn * 32;
        float cq[4][2];
        #pragma unroll
        for (int j = 0; j < 4; j++) {
            cq[j][0] = g_cbsq[cbase + j * 8 + tig * 2];
            cq[j][1] = g_cbsq[cbase + j * 8 + tig * 2 + 1];
        }
        float lmin[2][2] = {{3.4e38f, 3.4e38f}, {3.4e38f, 3.4e38f}};
        #pragma unroll
        for (int i = 0; i < 2; i++)
            #pragma unroll
            for (int j = 0; j < 4; j++) {
                float s00 = fmaf(-SCORE_K, (float)d[i][j][0], cq[j][0]);
                float s01 = fmaf(-SCORE_K, (float)d[i][j][1], cq[j][1]);
                float s10 = fmaf(-SCORE_K, (float)d[i][j][2], cq[j][0]);
                float s11 = fmaf(-SCORE_K, (float)d[i][j][3], cq[j][1]);
                lmin[i][0] = fminf(lmin[i][0], fminf(s00, s01));
                lmin[i][1] = fminf(lmin[i][1], fminf(s10, s11));
            }
        #pragma unroll
        for (int i = 0; i < 2; i++) {
            atomicMin(&s_rowkey[lr[i][0]], fkey(lmin[i][0]));
            atomicMin(&s_rowkey[lr[i][1]], fkey(lmin[i][1]));
        }
        __syncthreads();     // mins folded; ALL warps done reading Bs

        // issue B(nt+1) (safe post-barrier; overlaps register epilogue + peer CTA)
        if (nt + 1 < NT_CNT) ISSUE_B(nt + 1);
        CP_COMMIT();

        // epilogue phase 2: insert candidates vs tightened threshold
        #pragma unroll
        for (int i = 0; i < 2; i++)
            #pragma unroll
            for (int h = 0; h < 2; h++) {
                float thr = funkey(s_rowkey[lr[i][h]]) + RESCUE_DELTA;
                #pragma unroll
                for (int j = 0; j < 4; j++) {
                    float sa = fmaf(-SCORE_K, (float)d[i][j][h * 2 + 0], cq[j][0]);
                    float sb = fmaf(-SCORE_K, (float)d[i][j][h * 2 + 1], cq[j][1]);
                    int c = cbase + j * 8 + tig * 2;
                    if (sa <= thr) {
                        int pos = atomicAdd(&s_cnt[lr[i][h]], 1);
                        if (pos < CAND_MAX) s_cand[lr[i][h]][pos] = (uint16_t)c;
                    }
                    if (sb <= thr) {
                        int pos = atomicAdd(&s_cnt[lr[i][h]], 1);
                        if (pos < CAND_MAX) s_cand[lr[i][h]][pos] = (uint16_t)(c + 1);
                    }
                }
            }
    }

    __syncthreads();
    if (tid < G2_BM) {
        g_ncand[row0 + tid] = s_cnt[tid];
        #pragma unroll
        for (int i = 0; i < CAND_MAX / 8; i++)
            *(uint4*)&g_cand[row0 + tid][i * 8] = *(uint4*)&s_cand[tid][i * 8];
    }
}

// ---------------- kernel 3: exact rescue over candidates (validated R9-R14) ----------------
__global__ __launch_bounds__(256) void rescue_kernel(const float* __restrict__ X,
                                                     float* __restrict__ out) {
    int wid  = threadIdx.x >> 5;
    int lane = threadIdx.x & 31;
    int row  = blockIdx.x * 8 + wid;

    const float* xrow = X + (size_t)row * D_K;
    float x[32];
    #pragma unroll
    for (int t = 0; t < 32; t++) x[t] = xrow[lane + t * 32];

    float bestv = 3.4e38f;
    int   besti = C_N;
    int n = g_ncand[row];

    if (n <= CAND_MAX) {
        for (int i = 0; i < n; i++) {
            int c = g_cand[row][i];
            const float* urow = g_U + (size_t)c * D_K;
            float part = 0.f;
            #pragma unroll 8
            for (int t = 0; t < 32; t++)
                part = fmaf(x[t], urow[lane + t * 32], part);
            #pragma unroll
            for (int off = 16; off > 0; off >>= 1)
                part += __shfl_xor_sync(0xffffffffu, part, off);
            float sc = fmaf(-2.f, part, g_cbsq[c]);
            if (sc < bestv || (sc == bestv && c < besti)) { bestv = sc; besti = c; }
        }
    } else {
        for (int c = 0; c < C_N; c++) {
            const float* urow = g_U + (size_t)c * D_K;
            float part = 0.f;
            #pragma unroll 8
            for (int t = 0; t < 32; t++)
                part = fmaf(x[t], urow[lane + t * 32], part);
            #pragma unroll
            for (int off = 16; off > 0; off >>= 1)
                part += __shfl_xor_sync(0xffffffffu, part, off);
            float sc = fmaf(-2.f, part, g_cbsq[c]);
            if (sc < bestv) { bestv = sc; besti = c; }
        }
    }
    if (lane == 0) out[row] = (float)besti;
}

// ---------------- launch ----------------
extern "C" void kernel_launch(void* const* d_in, const int* in_sizes, int n_in,
                              void* d_out, int out_size) {
    (void)out_size;
    const float* X  = 0;
    const float* W  = 0;
    const float* CB = 0;
    for (int i = 0; i < n_in; i++) {
        long long s = (long long)in_sizes[i];
        if      (s == (long long)M_TOTAL * D_K) X  = (const float*)d_in[i];
        else if (s == (long long)Q_N * D_K)     W  = (const float*)d_in[i];
        else if (s == (long long)Q_N * C_N)     CB = (const float*)d_in[i];
    }
    if (!X)  X  = (const float*)d_in[0];
    if (!W  && n_in > 2) W  = (const float*)d_in[2];
    if (!CB && n_in > 3) CB = (const float*)d_in[3];

    float* out = (float*)d_out;

    cudaFuncSetAttribute(gemm2_tc_kernel,
                         cudaFuncAttributeMaxDynamicSharedMemorySize, G2_SMEM);

    prep_kernel<<<64 + 2048 + 256, 256>>>(CB, W);
    ugemm_kernel<<<dim3(C_N / 128, D_K / 64), 256>>>(CB, W);
    gemm1b_kernel<<<dim3(M_TOTAL / 128, Q_N / 128), 256>>>(X);
    gemm2_tc_kernel<<<M_TOTAL / G2_BM, G2_THREADS, G2_SMEM>>>();
    rescue_kernel<<<M_TOTAL / 8, 256>>>(X, out);
}

// round 16
// speedup vs baseline: 36.7828x; 1.0307x over previous
#include <cuda_runtime.h>
#include <cuda_bf16.h>
#include <cstdint>

// Problem constants (fixed shapes from reference)
#define M_TOTAL 16384   // B*L
#define D_K     1024    // D
#define Q_N     256     // Q
#define C_N     4096    // C

#define CAND_MAX 32
#define RESCUE_DELTA 8.0f
#define T_SCALE  18.0f
#define CB_SCALE 23.0f
#define X_SCALE  24.0f
#define W_SCALE  1850.0f
#define SCORE_K  (2.0f / (T_SCALE * CB_SCALE))
#define G1_OUT   (T_SCALE / (X_SCALE * W_SCALE))

// Scratch (device globals: allowed; no allocation APIs)
__device__ float          g_cbsq[C_N];            // ||codebook[:,c]||^2 (fp32 exact)
__device__ int8_t         g_W8[Q_N * D_K];        // int8 W (256KB), [n][k]
__device__ int8_t         g_T8[M_TOTAL * Q_N];    // int8 targets (4MB), [r][k]
__device__ int8_t         g_CB8[C_N * Q_N];       // int8 codebook (1MB), [c][k]
__device__ float          g_U[(size_t)C_N * D_K]; // U[c][d] = sum_q CB[q][c] W[q][d] (16MB)
__device__ int            g_ncand[M_TOTAL];
__device__ uint16_t       g_cand[M_TOTAL][CAND_MAX];

// ---------------- packed fp32x2 helpers (FFMA2, validated R5/R7) ----------------
__device__ __forceinline__ void fma2(unsigned long long& d,
                                     unsigned long long a,
                                     unsigned long long b) {
    asm("fma.rn.f32x2 %0, %1, %2, %0;" : "+l"(d) : "l"(a), "l"(b));
}
__device__ __forceinline__ unsigned long long pack2(float x) {
    unsigned long long r;
    unsigned u = __float_as_uint(x);
    asm("mov.b64 %0, {%1, %2};" : "=l"(r) : "r"(u), "r"(u));
    return r;
}
__device__ __forceinline__ float lo32(unsigned long long v) {
    return __uint_as_float((unsigned)(v & 0xffffffffull));
}
__device__ __forceinline__ float hi32(unsigned long long v) {
    return __uint_as_float((unsigned)(v >> 32));
}

// ---------------- warp MMA + ldmatrix + cp.async ----------------
__device__ __forceinline__ void mma16832s8(int* d, const uint32_t* a, const uint32_t* b) {
    asm volatile(
        "mma.sync.aligned.m16n8k32.row.col.s32.s8.s8.s32 "
        "{%0,%1,%2,%3}, {%4,%5,%6,%7}, {%8,%9}, {%0,%1,%2,%3};"
        : "+r"(d[0]), "+r"(d[1]), "+r"(d[2]), "+r"(d[3])
        : "r"(a[0]), "r"(a[1]), "r"(a[2]), "r"(a[3]), "r"(b[0]), "r"(b[1]));
}
__device__ __forceinline__ void ldsm_x4(uint32_t* r, uint32_t addr) {
    asm volatile("ldmatrix.sync.aligned.m8n8.x4.shared.b16 {%0,%1,%2,%3}, [%4];"
                 : "=r"(r[0]), "=r"(r[1]), "=r"(r[2]), "=r"(r[3]) : "r"(addr));
}
__device__ __forceinline__ void cp_async16(uint32_t dst, const void* src) {
    asm volatile("cp.async.cg.shared.global [%0], [%1], 16;" :: "r"(dst), "l"(src));
}
#define CP_COMMIT() asm volatile("cp.async.commit_group;" ::: "memory")
#define CP_WAIT0()  asm volatile("cp.async.wait_group 0;" ::: "memory")

__device__ __forceinline__ int q8(float v, float s) {
    int q = __float2int_rn(v * s);
    return q < -127 ? -127 : (q > 127 ? 127 : q);
}
__device__ __forceinline__ uint32_t pack4(int q0, int q1, int q2, int q3) {
    return (uint32_t)((q0 & 0xFF) | ((q1 & 0xFF) << 8) |
                      ((q2 & 0xFF) << 16) | ((q3 & 0xFF) << 24));
}

// order-preserving float<->uint key (for atomicMin on scores of any sign)
__device__ __forceinline__ uint32_t fkey(float f) {
    uint32_t b = __float_as_uint(f);
    return (b & 0x80000000u) ? ~b : (b | 0x80000000u);
}
__device__ __forceinline__ float funkey(uint32_t k) {
    uint32_t b = (k & 0x80000000u) ? (k & 0x7FFFFFFFu) : ~k;
    return __uint_as_float(b);
}

// ---------------- prep kernel: cbsq + convCB(int8) + convW(int8) fused ----------------
// blocks [0,64): cbsq | [64,2112): CB->s8 [c][k] | [2112,2368): W->s8 [n][k]
__global__ __launch_bounds__(256) void prep_kernel(const float* __restrict__ CB,
                                                   const float* __restrict__ W) {
    __shared__ float red[4][64];
    int b = blockIdx.x;
    int t = threadIdx.x;
    if (b < 64) {
        int c = b * 64 + (t & 63);
        int part = t >> 6;
        float s = 0.f;
        #pragma unroll 8
        for (int k = part * 64; k < part * 64 + 64; k++) {
            float v = CB[(size_t)k * C_N + c];
            s = fmaf(v, v, s);
        }
        red[part][t & 63] = s;
        __syncthreads();
        if (t < 64)
            g_cbsq[b * 64 + t] = red[0][t] + red[1][t] + red[2][t] + red[3][t];
    } else if (b < 2112) {
        int o2 = (b - 64) * 256 + t;        // pair index over 512K pairs
        int c  = o2 >> 7;
        int k2 = (o2 & 127) << 1;
        int q0 = q8(CB[(size_t)k2 * C_N + c], CB_SCALE);
        int q1 = q8(CB[(size_t)(k2 + 1) * C_N + c], CB_SCALE);
        *(uint16_t*)(g_CB8 + (size_t)c * Q_N + k2) =
            (uint16_t)((q0 & 0xFF) | ((q1 & 0xFF) << 8));
    } else {
        int idx = (b - 2112) * 256 + t;     // over 65536 float4s of W
        float4 v = ((const float4*)W)[idx];
        ((uint32_t*)g_W8)[idx] = pack4(q8(v.x, W_SCALE), q8(v.y, W_SCALE),
                                       q8(v.z, W_SCALE), q8(v.w, W_SCALE));
    }
}

// ---------------- kernel U: U = CB^T @ W  (fp32 FFMA2, validated R11) ----------------
__global__ __launch_bounds__(256) void ugemm_kernel(const float* __restrict__ CB,
                                                    const float* __restrict__ W) {
    __shared__ __align__(16) float As[32][128];
    __shared__ __align__(16) float Bs[32][64];
    int tid = threadIdx.x;
    int tr = tid >> 4;
    int tc = tid & 15;
    int row0 = blockIdx.x << 7;   // c
    int col0 = blockIdx.y << 6;   // d

    unsigned long long acc[4][4];
    #pragma unroll
    for (int p = 0; p < 4; p++)
        #pragma unroll
        for (int j = 0; j < 4; j++) acc[p][j] = 0ull;

    for (int kc = 0; kc < Q_N; kc += 32) {
        __syncthreads();
        #pragma unroll
        for (int i = 0; i < 4; i++) {
            int f4 = (i << 8) + tid;
            int q  = f4 >> 5;
            int e4 = (f4 & 31) << 2;
            *(float4*)&As[q][e4] = *(const float4*)(CB + (size_t)(kc + q) * C_N + row0 + e4);
        }
        #pragma unroll
        for (int i = 0; i < 2; i++) {
            int f4 = (i << 8) + tid;
            int q  = f4 >> 4;
            int e4 = (f4 & 15) << 2;
            *(float4*)&Bs[q][e4] = *(const float4*)(W + (size_t)(kc + q) * D_K + col0 + e4);
        }
        __syncthreads();
        #pragma unroll
        for (int k = 0; k < 32; k++) {
            ulonglong2 a01 = *(const ulonglong2*)&As[k][tr << 3];
            ulonglong2 a23 = *(const ulonglong2*)&As[k][(tr << 3) + 4];
            float4 b = *(const float4*)&Bs[k][tc << 2];
            unsigned long long bb0 = pack2(b.x), bb1 = pack2(b.y);
            unsigned long long bb2 = pack2(b.z), bb3 = pack2(b.w);
            fma2(acc[0][0], a01.x, bb0); fma2(acc[0][1], a01.x, bb1);
            fma2(acc[0][2], a01.x, bb2); fma2(acc[0][3], a01.x, bb3);
            fma2(acc[1][0], a01.y, bb0); fma2(acc[1][1], a01.y, bb1);
            fma2(acc[1][2], a01.y, bb2); fma2(acc[1][3], a01.y, bb3);
            fma2(acc[2][0], a23.x, bb0); fma2(acc[2][1], a23.x, bb1);
            fma2(acc[2][2], a23.x, bb2); fma2(acc[2][3], a23.x, bb3);
            fma2(acc[3][0], a23.y, bb0); fma2(acc[3][1], a23.y, bb1);
            fma2(acc[3][2], a23.y, bb2); fma2(acc[3][3], a23.y, bb3);
        }
    }
    #pragma unroll
    for (int p = 0; p < 4; p++) {
        int c = row0 + (tr << 3) + (p << 1);
        #pragma unroll
        for (int j = 0; j < 4; j++) {
            int d = col0 + (tc << 2) + j;
            g_U[(size_t)c       * D_K + d] = lo32(acc[p][j]);
            g_U[(size_t)(c + 1) * D_K + d] = hi32(acc[p][j]);
        }
    }
}

// ---------------- kernel 1: T8 = s8 gemm of quantized X @ W^T ----------------
// M=16384, N=256 (grid.y=2 x BN=128), K=1024 in 8 chunks of 128 bytes.
// 8 warps 4m x 2n: warp tile 32 x 64.  X quantized to s8 in-flight at staging.
#define G1_STRIDE 144   // 128 + 16 pad: 4-bank row offset, conflict-free ldsm
__global__ __launch_bounds__(256, 2) void gemm1s8_kernel(const float* __restrict__ X) {
    __shared__ __align__(16) int8_t As8[128 * G1_STRIDE];
    __shared__ __align__(16) int8_t Bs8[128 * G1_STRIDE];

    int tid  = threadIdx.x;
    int wid  = tid >> 5;
    int lane = tid & 31;
    int q    = lane >> 2;
    int tig  = lane & 3;
    int wm   = wid & 3;        // rows wm*32..+31
    int wn   = wid >> 2;       // cols wn*64..+63
    int row0 = blockIdx.x << 7;
    int col0 = blockIdx.y << 7;

    uint32_t asb = (uint32_t)__cvta_generic_to_shared(As8);
    uint32_t bsb = (uint32_t)__cvta_generic_to_shared(Bs8);

    // ldsm lane addresses (validated s8 fake-b16 pattern from R15 gemm2)
    int g = lane >> 3, idx = lane & 7;
    uint32_t aaddr[2], baddr[4];
    #pragma unroll
    for (int i = 0; i < 2; i++) {
        int r = wm * 32 + i * 16 + ((g & 1) << 3) + idx;
        aaddr[i] = asb + (uint32_t)(r * G1_STRIDE + ((g >> 1) << 4));
    }
    #pragma unroll
    for (int jp = 0; jp < 4; jp++) {
        int r = wn * 64 + jp * 16 + ((g >> 1) << 3) + idx;
        baddr[jp] = bsb + (uint32_t)(r * G1_STRIDE + ((g & 1) << 4));
    }

    int d[2][8][4];
    #pragma unroll
    for (int i = 0; i < 2; i++)
        #pragma unroll
        for (int j = 0; j < 8; j++)
            #pragma unroll
            for (int e = 0; e < 4; e++) d[i][j][e] = 0;

    for (int kc = 0; kc < D_K; kc += 128) {
        __syncthreads();     // all readers of previous chunk done
        // stage A: quantize fp32 X -> s8.  4096 float4 / 256 thr = 16 each.
        #pragma unroll
        for (int i = 0; i < 16; i++) {
            int id  = (i << 8) + tid;
            int row = id >> 5;            // 0..127
            int f4c = id & 31;            // float4 col within chunk
            float4 v = *(const float4*)(X + (size_t)(row0 + row) * D_K + kc + (f4c << 2));
            *(uint32_t*)(As8 + row * G1_STRIDE + (f4c << 2)) =
                pack4(q8(v.x, X_SCALE), q8(v.y, X_SCALE),
                      q8(v.z, X_SCALE), q8(v.w, X_SCALE));
        }
        // stage B: s8 W rows, cp.async 16B.  1024 uint4 / 256 thr = 4 each.
        #pragma unroll
        for (int i = 0; i < 4; i++) {
            int id  = (i << 8) + tid;
            int row = id >> 3;            // 0..127
            int kb  = (id & 7) << 4;      // 0..112
            cp_async16(bsb + (uint32_t)(row * G1_STRIDE + kb),
                       g_W8 + (size_t)(col0 + row) * D_K + kc + kb);
        }
        CP_COMMIT();
        CP_WAIT0();
        __syncthreads();
        #pragma unroll
        for (int ks = 0; ks < 4; ks++) {
            uint32_t koff = (uint32_t)(ks * 32);
            uint32_t a[2][4], b[4][4];
            ldsm_x4(a[0], aaddr[0] + koff);
            ldsm_x4(a[1], aaddr[1] + koff);
            #pragma unroll
            for (int jp = 0; jp < 4; jp++) ldsm_x4(b[jp], baddr[jp] + koff);
            #pragma unroll
            for (int i = 0; i < 2; i++)
                #pragma unroll
                for (int jp = 0; jp < 4; jp++) {
                    mma16832s8(d[i][jp * 2 + 0], a[i], &b[jp][0]);
                    mma16832s8(d[i][jp * 2 + 1], a[i], &b[jp][2]);
                }
        }
    }
    // epilogue: rescale int accumulators -> int8 T at T_SCALE
    #pragma unroll
    for (int j = 0; j < 8; j++) {
        int c = col0 + wn * 64 + j * 8 + tig * 2;
        #pragma unroll
        for (int i = 0; i < 2; i++) {
            int r = row0 + wm * 32 + i * 16 + q;
            int q0 = q8((float)d[i][j][0], G1_OUT), q1 = q8((float)d[i][j][1], G1_OUT);
            int q2 = q8((float)d[i][j][2], G1_OUT), q3 = q8((float)d[i][j][3], G1_OUT);
            *(uint16_t*)(g_T8 + (size_t)r * Q_N + c) =
                (uint16_t)((q0 & 0xFF) | ((q1 & 0xFF) << 8));
            *(uint16_t*)(g_T8 + (size_t)(r + 8) * Q_N + c) =
                (uint16_t)((q2 & 0xFF) | ((q3 & 0xFF) << 8));
        }
    }
}

// ---------------- kernel 2: int8 filter GEMM (byte-identical to R15 winner) ----------------
#define A8STRIDE 272           // bytes per row (256 + 16 pad)
#define G2_BM   64
#define G2_BN   128
#define G2_THREADS 256
#define G2_SMEM ((G2_BM + G2_BN) * A8STRIDE)   // 52224 bytes dynamic
#define NT_CNT  (C_N / G2_BN)                   // 32

__global__ __launch_bounds__(G2_THREADS, 2) void gemm2_tc_kernel() {
    extern __shared__ __align__(16) uint8_t sm8[];
    uint8_t* As = sm8;                        // [64][272]
    uint8_t* Bs = sm8 + G2_BM * A8STRIDE;     // [128][272]
    __shared__ uint32_t s_rowkey[G2_BM];
    __shared__ int      s_cnt[G2_BM];
    __shared__ uint16_t s_cand[G2_BM][CAND_MAX];

    int tid  = threadIdx.x;
    int lane = tid & 31;
    int wid  = tid >> 5;       // 0..7
    int q    = lane >> 2;
    int tig  = lane & 3;
    int wm   = wid & 1;        // rows wm*32..+31
    int wn   = wid >> 1;       // cols wn*32..+31 within 128-chunk
    int row0 = blockIdx.x * G2_BM;

    if (tid < G2_BM) { s_rowkey[tid] = 0xFFFFFFFFu; s_cnt[tid] = 0; }

    // stage resident A: 64 rows x 16 uint4 = 1024 uint4 / 256 thr = 4 each
    #pragma unroll
    for (int i = 0; i < 4; i++) {
        int id  = (i << 8) + tid;
        int row = id >> 4;
        int kb  = (id & 15) << 4;
        *(uint4*)(As + row * A8STRIDE + kb) =
            *(const uint4*)(g_T8 + (size_t)(row0 + row) * Q_N + kb);
    }

    uint32_t bsb = (uint32_t)__cvta_generic_to_shared(Bs);

    int g = lane >> 3, idx = lane & 7;
    uint32_t aaddr[2], baddr[2];
    #pragma unroll
    for (int i = 0; i < 2; i++) {
        int r = wm * 32 + i * 16 + ((g & 1) << 3) + idx;
        aaddr[i] = (uint32_t)__cvta_generic_to_shared(As + r * A8STRIDE + ((g >> 1) << 4));
    }
    #pragma unroll
    for (int jp = 0; jp < 2; jp++) {
        int r = wn * 32 + jp * 16 + ((g >> 1) << 3) + idx;
        baddr[jp] = bsb + (uint32_t)(r * A8STRIDE + ((g & 1) << 4));
    }

    #define ISSUE_B(nt_)                                                            \
        do {                                                                        \
            const int8_t* src = g_CB8 + (size_t)((nt_) * G2_BN) * Q_N;              \
            _Pragma("unroll")                                                       \
            for (int i_ = 0; i_ < 8; i_++) {                                        \
                int id_  = (i_ << 8) + tid;                                         \
                int row_ = id_ >> 4;                                                \
                int kb_  = (id_ & 15) << 4;                                         \
                cp_async16(bsb + (uint32_t)(row_ * A8STRIDE + kb_),                 \
                           src + (size_t)row_ * Q_N + kb_);                         \
            }                                                                       \
        } while (0)

    ISSUE_B(0); CP_COMMIT();

    int lr[2][2];
    #pragma unroll
    for (int i = 0; i < 2; i++) {
        lr[i][0] = wm * 32 + i * 16 + q;
        lr[i][1] = lr[i][0] + 8;
    }

    for (int nt = 0; nt < NT_CNT; nt++) {
        CP_WAIT0();
        __syncthreads();

        int d[2][4][4];
        #pragma unroll
        for (int i = 0; i < 2; i++)
            #pragma unroll
            for (int j = 0; j < 4; j++)
                #pragma unroll
                for (int e = 0; e < 4; e++) d[i][j][e] = 0;

        #pragma unroll
        for (int ks = 0; ks < 8; ks++) {      // K=256, 32 per mma
            uint32_t koff = (uint32_t)(ks * 32);
            uint32_t a[2][4], b[2][4];
            ldsm_x4(a[0], aaddr[0] + koff);
            ldsm_x4(a[1], aaddr[1] + koff);
            ldsm_x4(b[0], baddr[0] + koff);
            ldsm_x4(b[1], baddr[1] + koff);
            #pragma unroll
            for (int i = 0; i < 2; i++) {
                mma16832s8(d[i][0], a[i], &b[0][0]);
                mma16832s8(d[i][1], a[i], &b[0][2]);
                mma16832s8(d[i][2], a[i], &b[1][0]);
                mma16832s8(d[i][3], a[i], &b[1][2]);
            }
        }

        int cbase = nt * G2_BN + wn * 32;
        float cq[4][2];
        #pragma unroll
        for (int j = 0; j < 4; j++) {
            cq[j][0] = g_cbsq[cbase + j * 8 + tig * 2];
            cq[j][1] = g_cbsq[cbase + j * 8 + tig * 2 + 1];
        }
        float lmin[2][2] = {{3.4e38f, 3.4e38f}, {3.4e38f, 3.4e38f}};
        #pragma unroll
        for (int i = 0; i < 2; i++)
            #pragma unroll
            for (int j = 0; j < 4; j++) {
                float s00 = fmaf(-SCORE_K, (float)d[i][j][0], cq[j][0]);
                float s01 = fmaf(-SCORE_K, (float)d[i][j][1], cq[j][1]);
                float s10 = fmaf(-SCORE_K, (float)d[i][j][2], cq[j][0]);
                float s11 = fmaf(-SCORE_K, (float)d[i][j][3], cq[j][1]);
                lmin[i][0] = fminf(lmin[i][0], fminf(s00, s01));
                lmin[i][1] = fminf(lmin[i][1], fminf(s10, s11));
            }
        #pragma unroll
        for (int i = 0; i < 2; i++) {
            atomicMin(&s_rowkey[lr[i][0]], fkey(lmin[i][0]));
            atomicMin(&s_rowkey[lr[i][1]], fkey(lmin[i][1]));
        }
        __syncthreads();

        if (nt + 1 < NT_CNT) ISSUE_B(nt + 1);
        CP_COMMIT();

        #pragma unroll
        for (int i = 0; i < 2; i++)
            #pragma unroll
            for (int h = 0; h < 2; h++) {
                float thr = funkey(s_rowkey[lr[i][h]]) + RESCUE_DELTA;
                #pragma unroll
                for (int j = 0; j < 4; j++) {
                    float sa = fmaf(-SCORE_K, (float)d[i][j][h * 2 + 0], cq[j][0]);
                    float sb = fmaf(-SCORE_K, (float)d[i][j][h * 2 + 1], cq[j][1]);
                    int c = cbase + j * 8 + tig * 2;
                    if (sa <= thr) {
                        int pos = atomicAdd(&s_cnt[lr[i][h]], 1);
                        if (pos < CAND_MAX) s_cand[lr[i][h]][pos] = (uint16_t)c;
                    }
                    if (sb <= thr) {
                        int pos = atomicAdd(&s_cnt[lr[i][h]], 1);
                        if (pos < CAND_MAX) s_cand[lr[i][h]][pos] = (uint16_t)(c + 1);
                    }
                }
            }
    }

    __syncthreads();
    if (tid < G2_BM) {
        g_ncand[row0 + tid] = s_cnt[tid];
        #pragma unroll
        for (int i = 0; i < CAND_MAX / 8; i++)
            *(uint4*)&g_cand[row0 + tid][i * 8] = *(uint4*)&s_cand[tid][i * 8];
    }
}

// ---------------- kernel 3: exact rescue over candidates (validated R9-R15) ----------------
__global__ __launch_bounds__(256) void rescue_kernel(const float* __restrict__ X,
                                                     float* __restrict__ out) {
    int wid  = threadIdx.x >> 5;
    int lane = threadIdx.x & 31;
    int row  = blockIdx.x * 8 + wid;

    const float* xrow = X + (size_t)row * D_K;
    float x[32];
    #pragma unroll
    for (int t = 0; t < 32; t++) x[t] = xrow[lane + t * 32];

    float bestv = 3.4e38f;
    int   besti = C_N;
    int n = g_ncand[row];

    if (n <= CAND_MAX) {
        for (int i = 0; i < n; i++) {
            int c = g_cand[row][i];
            const float* urow = g_U + (size_t)c * D_K;
            float part = 0.f;
            #pragma unroll 8
            for (int t = 0; t < 32; t++)
                part = fmaf(x[t], urow[lane + t * 32], part);
            #pragma unroll
            for (int off = 16; off > 0; off >>= 1)
                part += __shfl_xor_sync(0xffffffffu, part, off);
            float sc = fmaf(-2.f, part, g_cbsq[c]);
            if (sc < bestv || (sc == bestv && c < besti)) { bestv = sc; besti = c; }
        }
    } else {
        for (int c = 0; c < C_N; c++) {
            const float* urow = g_U + (size_t)c * D_K;
            float part = 0.f;
            #pragma unroll 8
            for (int t = 0; t < 32; t++)
                part = fmaf(x[t], urow[lane + t * 32], part);
            #pragma unroll
            for (int off = 16; off > 0; off >>= 1)
                part += __shfl_xor_sync(0xffffffffu, part, off);
            float sc = fmaf(-2.f, part, g_cbsq[c]);
            if (sc < bestv) { bestv = sc; besti = c; }
        }
    }
    if (lane == 0) out[row] = (float)besti;
}

// ---------------- launch ----------------
extern "C" void kernel_launch(void* const* d_in, const int* in_sizes, int n_in,
                              void* d_out, int out_size) {
    (void)out_size;
    const float* X  = 0;
    const float* W  = 0;
    const float* CB = 0;
    for (int i = 0; i < n_in; i++) {
        long long s = (long long)in_sizes[i];
        if      (s == (long long)M_TOTAL * D_K) X  = (const float*)d_in[i];
        else if (s == (long long)Q_N * D_K)     W  = (const float*)d_in[i];
        else if (s == (long long)Q_N * C_N)     CB = (const float*)d_in[i];
    }
    if (!X)  X  = (const float*)d_in[0];
    if (!W  && n_in > 2) W  = (const float*)d_in[2];
    if (!CB && n_in > 3) CB = (const float*)d_in[3];

    float* out = (float*)d_out;

    cudaFuncSetAttribute(gemm2_tc_kernel,
                         cudaFuncAttributeMaxDynamicSharedMemorySize, G2_SMEM);

    prep_kernel<<<64 + 2048 + 256, 256>>>(CB, W);
    ugemm_kernel<<<dim3(C_N / 128, D_K / 64), 256>>>(CB, W);
    gemm1s8_kernel<<<dim3(M_TOTAL / 128, Q_N / 128), 256>>>(X);
    gemm2_tc_kernel<<<M_TOTAL / G2_BM, G2_THREADS, G2_SMEM>>>();
    rescue_kernel<<<M_TOTAL / 8, 256>>>(X, out);
}

// round 17
// speedup vs baseline: 37.3666x; 1.0159x over previous
#include <cuda_runtime.h>
#include <cuda_bf16.h>
#include <cstdint>

// Problem constants (fixed shapes from reference)
#define M_TOTAL 16384   // B*L
#define D_K     1024    // D
#define Q_N     256     // Q
#define C_N     4096    // C

#define CAND_MAX 32
#define RESCUE_DELTA 8.0f
#define T_SCALE  18.0f
#define CB_SCALE 23.0f
#define X_SCALE  24.0f
#define W_SCALE  1850.0f
#define SCORE_K  (2.0f / (T_SCALE * CB_SCALE))
#define G1_OUT   (T_SCALE / (X_SCALE * W_SCALE))

// Scratch (device globals: allowed; no allocation APIs)
__device__ float          g_cbsq[C_N];            // ||codebook[:,c]||^2 (fp32 exact)
__device__ int8_t         g_W8[Q_N * D_K];        // int8 W (256KB), [n][k]
__device__ int8_t         g_T8[M_TOTAL * Q_N];    // int8 targets (4MB), [r][k]
__device__ int8_t         g_CB8[C_N * Q_N];       // int8 codebook (1MB), [c][k]
__device__ float          g_U[(size_t)C_N * D_K]; // U[c][d] (16MB)
__device__ int            g_ncand[M_TOTAL];
__device__ uint16_t       g_cand[M_TOTAL][CAND_MAX];

// ---------------- packed fp32x2 helpers (FFMA2, validated R5/R7) ----------------
__device__ __forceinline__ void fma2(unsigned long long& d,
                                     unsigned long long a,
                                     unsigned long long b) {
    asm("fma.rn.f32x2 %0, %1, %2, %0;" : "+l"(d) : "l"(a), "l"(b));
}
__device__ __forceinline__ unsigned long long pack2(float x) {
    unsigned long long r;
    unsigned u = __float_as_uint(x);
    asm("mov.b64 %0, {%1, %2};" : "=l"(r) : "r"(u), "r"(u));
    return r;
}
__device__ __forceinline__ float lo32(unsigned long long v) {
    return __uint_as_float((unsigned)(v & 0xffffffffull));
}
__device__ __forceinline__ float hi32(unsigned long long v) {
    return __uint_as_float((unsigned)(v >> 32));
}

// ---------------- warp MMA + ldmatrix + cp.async ----------------
__device__ __forceinline__ void mma16832s8(int* d, const uint32_t* a, const uint32_t* b) {
    asm volatile(
        "mma.sync.aligned.m16n8k32.row.col.s32.s8.s8.s32 "
        "{%0,%1,%2,%3}, {%4,%5,%6,%7}, {%8,%9}, {%0,%1,%2,%3};"
        : "+r"(d[0]), "+r"(d[1]), "+r"(d[2]), "+r"(d[3])
        : "r"(a[0]), "r"(a[1]), "r"(a[2]), "r"(a[3]), "r"(b[0]), "r"(b[1]));
}
__device__ __forceinline__ void ldsm_x4(uint32_t* r, uint32_t addr) {
    asm volatile("ldmatrix.sync.aligned.m8n8.x4.shared.b16 {%0,%1,%2,%3}, [%4];"
                 : "=r"(r[0]), "=r"(r[1]), "=r"(r[2]), "=r"(r[3]) : "r"(addr));
}
__device__ __forceinline__ void cp_async16(uint32_t dst, const void* src) {
    asm volatile("cp.async.cg.shared.global [%0], [%1], 16;" :: "r"(dst), "l"(src));
}
#define CP_COMMIT() asm volatile("cp.async.commit_group;" ::: "memory")
#define CP_WAIT0()  asm volatile("cp.async.wait_group 0;" ::: "memory")

__device__ __forceinline__ int q8(float v, float s) {
    int q = __float2int_rn(v * s);
    return q < -127 ? -127 : (q > 127 ? 127 : q);
}
__device__ __forceinline__ uint32_t pack4(int q0, int q1, int q2, int q3) {
    return (uint32_t)((q0 & 0xFF) | ((q1 & 0xFF) << 8) |
                      ((q2 & 0xFF) << 16) | ((q3 & 0xFF) << 24));
}

// order-preserving float<->uint key (for atomicMin on scores of any sign)
__device__ __forceinline__ uint32_t fkey(float f) {
    uint32_t b = __float_as_uint(f);
    return (b & 0x80000000u) ? ~b : (b | 0x80000000u);
}
__device__ __forceinline__ float funkey(uint32_t k) {
    uint32_t b = (k & 0x80000000u) ? (k & 0x7FFFFFFFu) : ~k;
    return __uint_as_float(b);
}

// ---------------- prep kernel: cbsq + convCB(int8) + convW(int8) fused ----------------
__global__ __launch_bounds__(256) void prep_kernel(const float* __restrict__ CB,
                                                   const float* __restrict__ W) {
    __shared__ float red[4][64];
    int b = blockIdx.x;
    int t = threadIdx.x;
    if (b < 64) {
        int c = b * 64 + (t & 63);
        int part = t >> 6;
        float s = 0.f;
        #pragma unroll 8
        for (int k = part * 64; k < part * 64 + 64; k++) {
            float v = CB[(size_t)k * C_N + c];
            s = fmaf(v, v, s);
        }
        red[part][t & 63] = s;
        __syncthreads();
        if (t < 64)
            g_cbsq[b * 64 + t] = red[0][t] + red[1][t] + red[2][t] + red[3][t];
    } else if (b < 2112) {
        int o2 = (b - 64) * 256 + t;
        int c  = o2 >> 7;
        int k2 = (o2 & 127) << 1;
        int q0 = q8(CB[(size_t)k2 * C_N + c], CB_SCALE);
        int q1 = q8(CB[(size_t)(k2 + 1) * C_N + c], CB_SCALE);
        *(uint16_t*)(g_CB8 + (size_t)c * Q_N + k2) =
            (uint16_t)((q0 & 0xFF) | ((q1 & 0xFF) << 8));
    } else {
        int idx = (b - 2112) * 256 + t;
        float4 v = ((const float4*)W)[idx];
        ((uint32_t*)g_W8)[idx] = pack4(q8(v.x, W_SCALE), q8(v.y, W_SCALE),
                                       q8(v.z, W_SCALE), q8(v.w, W_SCALE));
    }
}

// ---------------- FUSED mid kernel: ugemm (blocks 0..511)  ∪  gemm1s8 (512..767) ----
// ugemm: U = CB^T @ W, fp32 FFMA2, BM=128 BN=64 BK=32 (R11-validated body).
// gemm1s8: T8 = q8(X) @ q8(W)^T via s8 mma (R16-validated body).
// Both bodies unchanged except smem carved from dynamic pool and index bases.
#define G1_STRIDE 144
#define MID_SMEM  (128 * G1_STRIDE * 2)   // 36864 >= ugemm's 24576

__global__ __launch_bounds__(256, 2) void mid_kernel(const float* __restrict__ CB,
                                                     const float* __restrict__ W,
                                                     const float* __restrict__ X) {
    extern __shared__ __align__(16) uint8_t smraw[];
    int tid = threadIdx.x;

    if (blockIdx.x < 512) {
        // ================= ugemm branch =================
        float* As = (float*)smraw;              // [32][128]
        float* Bs = As + 32 * 128;              // [32][64]
        int tr = tid >> 4;
        int tc = tid & 15;
        int row0 = (blockIdx.x & 31) << 7;      // c
        int col0 = (blockIdx.x >> 5) << 6;      // d

        unsigned long long acc[4][4];
        #pragma unroll
        for (int p = 0; p < 4; p++)
            #pragma unroll
            for (int j = 0; j < 4; j++) acc[p][j] = 0ull;

        for (int kc = 0; kc < Q_N; kc += 32) {
            __syncthreads();
            #pragma unroll
            for (int i = 0; i < 4; i++) {
                int f4 = (i << 8) + tid;
                int q  = f4 >> 5;
                int e4 = (f4 & 31) << 2;
                *(float4*)(As + q * 128 + e4) =
                    *(const float4*)(CB + (size_t)(kc + q) * C_N + row0 + e4);
            }
            #pragma unroll
            for (int i = 0; i < 2; i++) {
                int f4 = (i << 8) + tid;
                int q  = f4 >> 4;
                int e4 = (f4 & 15) << 2;
                *(float4*)(Bs + q * 64 + e4) =
                    *(const float4*)(W + (size_t)(kc + q) * D_K + col0 + e4);
            }
            __syncthreads();
            #pragma unroll
            for (int k = 0; k < 32; k++) {
                ulonglong2 a01 = *(const ulonglong2*)(As + k * 128 + (tr << 3));
                ulonglong2 a23 = *(const ulonglong2*)(As + k * 128 + (tr << 3) + 4);
                float4 b = *(const float4*)(Bs + k * 64 + (tc << 2));
                unsigned long long bb0 = pack2(b.x), bb1 = pack2(b.y);
                unsigned long long bb2 = pack2(b.z), bb3 = pack2(b.w);
                fma2(acc[0][0], a01.x, bb0); fma2(acc[0][1], a01.x, bb1);
                fma2(acc[0][2], a01.x, bb2); fma2(acc[0][3], a01.x, bb3);
                fma2(acc[1][0], a01.y, bb0); fma2(acc[1][1], a01.y, bb1);
                fma2(acc[1][2], a01.y, bb2); fma2(acc[1][3], a01.y, bb3);
                fma2(acc[2][0], a23.x, bb0); fma2(acc[2][1], a23.x, bb1);
                fma2(acc[2][2], a23.x, bb2); fma2(acc[2][3], a23.x, bb3);
                fma2(acc[3][0], a23.y, bb0); fma2(acc[3][1], a23.y, bb1);
                fma2(acc[3][2], a23.y, bb2); fma2(acc[3][3], a23.y, bb3);
            }
        }
        #pragma unroll
        for (int p = 0; p < 4; p++) {
            int c = row0 + (tr << 3) + (p << 1);
            #pragma unroll
            for (int j = 0; j < 4; j++) {
                int d = col0 + (tc << 2) + j;
                g_U[(size_t)c       * D_K + d] = lo32(acc[p][j]);
                g_U[(size_t)(c + 1) * D_K + d] = hi32(acc[p][j]);
            }
        }
    } else {
        // ================= gemm1s8 branch =================
        int8_t* As8 = (int8_t*)smraw;
        int8_t* Bs8 = (int8_t*)smraw + 128 * G1_STRIDE;
        int b2   = blockIdx.x - 512;
        int wid  = tid >> 5;
        int lane = tid & 31;
        int q    = lane >> 2;
        int tig  = lane & 3;
        int wm   = wid & 3;
        int wn   = wid >> 2;
        int row0 = (b2 & 127) << 7;
        int col0 = (b2 >> 7) << 7;

        uint32_t asb = (uint32_t)__cvta_generic_to_shared(As8);
        uint32_t bsb = (uint32_t)__cvta_generic_to_shared(Bs8);

        int g = lane >> 3, idx = lane & 7;
        uint32_t aaddr[2], baddr[4];
        #pragma unroll
        for (int i = 0; i < 2; i++) {
            int r = wm * 32 + i * 16 + ((g & 1) << 3) + idx;
            aaddr[i] = asb + (uint32_t)(r * G1_STRIDE + ((g >> 1) << 4));
        }
        #pragma unroll
        for (int jp = 0; jp < 4; jp++) {
            int r = wn * 64 + jp * 16 + ((g >> 1) << 3) + idx;
            baddr[jp] = bsb + (uint32_t)(r * G1_STRIDE + ((g & 1) << 4));
        }

        int d[2][8][4];
        #pragma unroll
        for (int i = 0; i < 2; i++)
            #pragma unroll
            for (int j = 0; j < 8; j++)
                #pragma unroll
                for (int e = 0; e < 4; e++) d[i][j][e] = 0;

        for (int kc = 0; kc < D_K; kc += 128) {
            __syncthreads();
            #pragma unroll
            for (int i = 0; i < 16; i++) {
                int id  = (i << 8) + tid;
                int row = id >> 5;
                int f4c = id & 31;
                float4 v = *(const float4*)(X + (size_t)(row0 + row) * D_K + kc + (f4c << 2));
                *(uint32_t*)(As8 + row * G1_STRIDE + (f4c << 2)) =
                    pack4(q8(v.x, X_SCALE), q8(v.y, X_SCALE),
                          q8(v.z, X_SCALE), q8(v.w, X_SCALE));
            }
            #pragma unroll
            for (int i = 0; i < 4; i++) {
                int id  = (i << 8) + tid;
                int row = id >> 3;
                int kb  = (id & 7) << 4;
                cp_async16(bsb + (uint32_t)(row * G1_STRIDE + kb),
                           g_W8 + (size_t)(col0 + row) * D_K + kc + kb);
            }
            CP_COMMIT();
            CP_WAIT0();
            __syncthreads();
            #pragma unroll
            for (int ks = 0; ks < 4; ks++) {
                uint32_t koff = (uint32_t)(ks * 32);
                uint32_t a[2][4], b[4][4];
                ldsm_x4(a[0], aaddr[0] + koff);
                ldsm_x4(a[1], aaddr[1] + koff);
                #pragma unroll
                for (int jp = 0; jp < 4; jp++) ldsm_x4(b[jp], baddr[jp] + koff);
                #pragma unroll
                for (int i = 0; i < 2; i++)
                    #pragma unroll
                    for (int jp = 0; jp < 4; jp++) {
                        mma16832s8(d[i][jp * 2 + 0], a[i], &b[jp][0]);
                        mma16832s8(d[i][jp * 2 + 1], a[i], &b[jp][2]);
                    }
            }
        }
        #pragma unroll
        for (int j = 0; j < 8; j++) {
            int c = col0 + wn * 64 + j * 8 + tig * 2;
            #pragma unroll
            for (int i = 0; i < 2; i++) {
                int r = row0 + wm * 32 + i * 16 + q;
                int q0 = q8((float)d[i][j][0], G1_OUT), q1 = q8((float)d[i][j][1], G1_OUT);
                int q2 = q8((float)d[i][j][2], G1_OUT), q3 = q8((float)d[i][j][3], G1_OUT);
                *(uint16_t*)(g_T8 + (size_t)r * Q_N + c) =
                    (uint16_t)((q0 & 0xFF) | ((q1 & 0xFF) << 8));
                *(uint16_t*)(g_T8 + (size_t)(r + 8) * Q_N + c) =
                    (uint16_t)((q2 & 0xFF) | ((q3 & 0xFF) << 8));
            }
        }
    }
}

// ---------------- kernel 2: int8 filter GEMM (byte-identical to R15 winner) ----------------
#define A8STRIDE 272
#define G2_BM   64
#define G2_BN   128
#define G2_THREADS 256
#define G2_SMEM ((G2_BM + G2_BN) * A8STRIDE)   // 52224 bytes dynamic
#define NT_CNT  (C_N / G2_BN)                   // 32

__global__ __launch_bounds__(G2_THREADS, 2) void gemm2_tc_kernel() {
    extern __shared__ __align__(16) uint8_t sm8[];
    uint8_t* As = sm8;
    uint8_t* Bs = sm8 + G2_BM * A8STRIDE;
    __shared__ uint32_t s_rowkey[G2_BM];
    __shared__ int      s_cnt[G2_BM];
    __shared__ uint16_t s_cand[G2_BM][CAND_MAX];

    int tid  = threadIdx.x;
    int lane = tid & 31;
    int wid  = tid >> 5;
    int q    = lane >> 2;
    int tig  = lane & 3;
    int wm   = wid & 1;
    int wn   = wid >> 1;
    int row0 = blockIdx.x * G2_BM;

    if (tid < G2_BM) { s_rowkey[tid] = 0xFFFFFFFFu; s_cnt[tid] = 0; }

    #pragma unroll
    for (int i = 0; i < 4; i++) {
        int id  = (i << 8) + tid;
        int row = id >> 4;
        int kb  = (id & 15) << 4;
        *(uint4*)(As + row * A8STRIDE + kb) =
            *(const uint4*)(g_T8 + (size_t)(row0 + row) * Q_N + kb);
    }

    uint32_t bsb = (uint32_t)__cvta_generic_to_shared(Bs);

    int g = lane >> 3, idx = lane & 7;
    uint32_t aaddr[2], baddr[2];
    #pragma unroll
    for (int i = 0; i < 2; i++) {
        int r = wm * 32 + i * 16 + ((g & 1) << 3) + idx;
        aaddr[i] = (uint32_t)__cvta_generic_to_shared(As + r * A8STRIDE + ((g >> 1) << 4));
    }
    #pragma unroll
    for (int jp = 0; jp < 2; jp++) {
        int r = wn * 32 + jp * 16 + ((g >> 1) << 3) + idx;
        baddr[jp] = bsb + (uint32_t)(r * A8STRIDE + ((g & 1) << 4));
    }

    #define ISSUE_B(nt_)                                                            \
        do {                                                                        \
            const int8_t* src = g_CB8 + (size_t)((nt_) * G2_BN) * Q_N;              \
            _Pragma("unroll")                                                       \
            for (int i_ = 0; i_ < 8; i_++) {                                        \
                int id_  = (i_ << 8) + tid;                                         \
                int row_ = id_ >> 4;                                                \
                int kb_  = (id_ & 15) << 4;                                         \
                cp_async16(bsb + (uint32_t)(row_ * A8STRIDE + kb_),                 \
                           src + (size_t)row_ * Q_N + kb_);                         \
            }                                                                       \
        } while (0)

    ISSUE_B(0); CP_COMMIT();

    int lr[2][2];
    #pragma unroll
    for (int i = 0; i < 2; i++) {
        lr[i][0] = wm * 32 + i * 16 + q;
        lr[i][1] = lr[i][0] + 8;
    }

    for (int nt = 0; nt < NT_CNT; nt++) {
        CP_WAIT0();
        __syncthreads();

        int d[2][4][4];
        #pragma unroll
        for (int i = 0; i < 2; i++)
            #pragma unroll
            for (int j = 0; j < 4; j++)
                #pragma unroll
                for (int e = 0; e < 4; e++) d[i][j][e] = 0;

        #pragma unroll
        for (int ks = 0; ks < 8; ks++) {
            uint32_t koff = (uint32_t)(ks * 32);
            uint32_t a[2][4], b[2][4];
            ldsm_x4(a[0], aaddr[0] + koff);
            ldsm_x4(a[1], aaddr[1] + koff);
            ldsm_x4(b[0], baddr[0] + koff);
            ldsm_x4(b[1], baddr[1] + koff);
            #pragma unroll
            for (int i = 0; i < 2; i++) {
                mma16832s8(d[i][0], a[i], &b[0][0]);
                mma16832s8(d[i][1], a[i], &b[0][2]);
                mma16832s8(d[i][2], a[i], &b[1][0]);
                mma16832s8(d[i][3], a[i], &b[1][2]);
            }
        }

        int cbase = nt * G2_BN + wn * 32;
        float cq[4][2];
        #pragma unroll
        for (int j = 0; j < 4; j++) {
            cq[j][0] = g_cbsq[cbase + j * 8 + tig * 2];
            cq[j][1] = g_cbsq[cbase + j * 8 + tig * 2 + 1];
        }
        float lmin[2][2] = {{3.4e38f, 3.4e38f}, {3.4e38f, 3.4e38f}};
        #pragma unroll
        for (int i = 0; i < 2; i++)
            #pragma unroll
            for (int j = 0; j < 4; j++) {
                float s00 = fmaf(-SCORE_K, (float)d[i][j][0], cq[j][0]);
                float s01 = fmaf(-SCORE_K, (float)d[i][j][1], cq[j][1]);
                float s10 = fmaf(-SCORE_K, (float)d[i][j][2], cq[j][0]);
                float s11 = fmaf(-SCORE_K, (float)d[i][j][3], cq[j][1]);
                lmin[i][0] = fminf(lmin[i][0], fminf(s00, s01));
                lmin[i][1] = fminf(lmin[i][1], fminf(s10, s11));
            }
        #pragma unroll
        for (int i = 0; i < 2; i++) {
            atomicMin(&s_rowkey[lr[i][0]], fkey(lmin[i][0]));
            atomicMin(&s_rowkey[lr[i][1]], fkey(lmin[i][1]));
        }
        __syncthreads();

        if (nt + 1 < NT_CNT) ISSUE_B(nt + 1);
        CP_COMMIT();

        #pragma unroll
        for (int i = 0; i < 2; i++)
            #pragma unroll
            for (int h = 0; h < 2; h++) {
                float thr = funkey(s_rowkey[lr[i][h]]) + RESCUE_DELTA;
                #pragma unroll
                for (int j = 0; j < 4; j++) {
                    float sa = fmaf(-SCORE_K, (float)d[i][j][h * 2 + 0], cq[j][0]);
                    float sb = fmaf(-SCORE_K, (float)d[i][j][h * 2 + 1], cq[j][1]);
                    int c = cbase + j * 8 + tig * 2;
                    if (sa <= thr) {
                        int pos = atomicAdd(&s_cnt[lr[i][h]], 1);
                        if (pos < CAND_MAX) s_cand[lr[i][h]][pos] = (uint16_t)c;
                    }
                    if (sb <= thr) {
                        int pos = atomicAdd(&s_cnt[lr[i][h]], 1);
                        if (pos < CAND_MAX) s_cand[lr[i][h]][pos] = (uint16_t)(c + 1);
                    }
                }
            }
    }

    __syncthreads();
    if (tid < G2_BM) {
        g_ncand[row0 + tid] = s_cnt[tid];
        #pragma unroll
        for (int i = 0; i < CAND_MAX / 8; i++)
            *(uint4*)&g_cand[row0 + tid][i * 8] = *(uint4*)&s_cand[tid][i * 8];
    }
}

// ---------------- kernel 3: exact rescue over candidates (validated R9-R16) ----------------
__global__ __launch_bounds__(256) void rescue_kernel(const float* __restrict__ X,
                                                     float* __restrict__ out) {
    int wid  = threadIdx.x >> 5;
    int lane = threadIdx.x & 31;
    int row  = blockIdx.x * 8 + wid;

    const float* xrow = X + (size_t)row * D_K;
    float x[32];
    #pragma unroll
    for (int t = 0; t < 32; t++) x[t] = xrow[lane + t * 32];

    float bestv = 3.4e38f;
    int   besti = C_N;
    int n = g_ncand[row];

    if (n <= CAND_MAX) {
        for (int i = 0; i < n; i++) {
            int c = g_cand[row][i];
            const float* urow = g_U + (size_t)c * D_K;
            float part = 0.f;
            #pragma unroll 8
            for (int t = 0; t < 32; t++)
                part = fmaf(x[t], urow[lane + t * 32], part);
            #pragma unroll
            for (int off = 16; off > 0; off >>= 1)
                part += __shfl_xor_sync(0xffffffffu, part, off);
            float sc = fmaf(-2.f, part, g_cbsq[c]);
            if (sc < bestv || (sc == bestv && c < besti)) { bestv = sc; besti = c; }
        }
    } else {
        for (int c = 0; c < C_N; c++) {
            const float* urow = g_U + (size_t)c * D_K;
            float part = 0.f;
            #pragma unroll 8
            for (int t = 0; t < 32; t++)
                part = fmaf(x[t], urow[lane + t * 32], part);
            #pragma unroll
            for (int off = 16; off > 0; off >>= 1)
                part += __shfl_xor_sync(0xffffffffu, part, off);
            float sc = fmaf(-2.f, part, g_cbsq[c]);
            if (sc < bestv) { bestv = sc; besti = c; }
        }
    }
    if (lane == 0) out[row] = (float)besti;
}

// ---------------- launch ----------------
extern "C" void kernel_launch(void* const* d_in, const int* in_sizes, int n_in,
                              void* d_out, int out_size) {
    (void)out_size;
    const float* X  = 0;
    const float* W  = 0;
    const float* CB = 0;
    for (int i = 0; i < n_in; i++) {
        long long s = (long long)in_sizes[i];
        if      (s == (long long)M_TOTAL * D_K) X  = (const float*)d_in[i];
        else if (s == (long long)Q_N * D_K)     W  = (const float*)d_in[i];
        else if (s == (long long)Q_N * C_N)     CB = (const float*)d_in[i];
    }
    if (!X)  X  = (const float*)d_in[0];
    if (!W  && n_in > 2) W  = (const float*)d_in[2];
    if (!CB && n_in > 3) CB = (const float*)d_in[3];

    float* out = (float*)d_out;

    cudaFuncSetAttribute(gemm2_tc_kernel,
                         cudaFuncAttributeMaxDynamicSharedMemorySize, G2_SMEM);

    prep_kernel<<<64 + 2048 + 256, 256>>>(CB, W);
    mid_kernel<<<512 + 256, 256, MID_SMEM>>>(CB, W, X);   // ugemm ∪ gemm1s8 (independent)
    gemm2_tc_kernel<<<M_TOTAL / G2_BM, G2_THREADS, G2_SMEM>>>();
    rescue_kernel<<<M_TOTAL / 8, 256>>>(X, out);
}